// round 12
// baseline (speedup 1.0000x reference)
#include <cuda_runtime.h>
#include <cstdint>

#define NN 2048
#define TT 4096
#define MAXS 256
#define C_CTAS 2
#define NPC 256            /* threads per CTA */
#define NPT 4              /* neurons per thread */
#define NPCN (NPC * NPT)   /* neurons per CTA = 1024 */
#define WARPS 8            /* warps per CTA */
#define NSLOTS 16          /* total publishing warps in cluster */
#define DEPTH 8            /* slot ring depth (skew bound is 2) */
#define PF 4               /* ic/ur prefetch depth (register ring) */
#define DT 2.44140625e-4f  /* (1-0)/4096, exact in fp32 */
#define ALPHA_F 0.01f
#define FULLM 0xffffffffu

__global__ void init_kernel(float* __restrict__ out) {
    int idx = blockIdx.x * blockDim.x + threadIdx.x;
    int stride = gridDim.x * blockDim.x;
    // Output layout: [ys (T*N*3)] [tev (256)] [yev (256*N*3)] [et (256*N)] [num_spikes (1)]
    float* tev = out + (size_t)TT * NN * 3;
    const int inf_n = MAXS + MAXS * NN * 3;          // tevents + yevents -> +inf
    const float finf = __int_as_float(0x7f800000);
    for (int t = idx; t < inf_n; t += stride) tev[t] = finf;
    float* et = tev + inf_n;
    const int et_n = MAXS * NN;                      // event_types -> 0
    for (int t = idx; t < et_n; t += stride) et[t] = 0.0f;
}

__device__ __forceinline__ unsigned ld_vol_shared(unsigned addr) {
    unsigned v;
    asm volatile("ld.volatile.shared.u32 %0, [%1];" : "=r"(v) : "r"(addr));
    return v;
}
__device__ __forceinline__ void st_shared_cluster(unsigned addr, unsigned v) {
    asm volatile("st.shared::cluster.u32 [%0], %1;" :: "r"(addr), "r"(v) : "memory");
}
__device__ __forceinline__ unsigned mapa_u32(unsigned addr, unsigned rank) {
    unsigned r;
    asm("mapa.shared::cluster.u32 %0, %1, %2;" : "=r"(r) : "r"(addr), "r"(rank));
    return r;
}
__device__ __forceinline__ unsigned smem_u32(const void* p) {
    unsigned a;
    asm("{ .reg .u64 t; cvta.to.shared.u64 t, %1; cvt.u32.u64 %0, t; }" : "=r"(a) : "l"(p));
    return a;
}

// Exact jax.nn.softplus(x) = max(x,0) + log1p(exp(-|x|))
__device__ __forceinline__ float softplus_ref(float v) {
    float ax = fabsf(v);
    float e  = expf(-ax);
    float l  = log1pf(e);
    return __fadd_rn(fmaxf(v, 0.0f), l);
}

__global__ void __launch_bounds__(NPC, 1) __cluster_dims__(C_CTAS, 1, 1)
sim_kernel(const float* __restrict__ w,  const float* __restrict__ mu,
           const float* __restrict__ v0, const float* __restrict__ i0,
           const float* __restrict__ ic, const float* __restrict__ u0,
           const float* __restrict__ ur, float* __restrict__ out)
{
    __shared__ __align__(16) unsigned slots[DEPTH * NSLOTS];  // [ring][16 warp slots]

    const int t    = threadIdx.x;
    const int lane = t & 31;
    const int wid  = t >> 5;
    const int cta  = blockIdx.x;                 // cluster rank (grid == 1 cluster)
    const int nb   = cta * NPCN + t;             // neuron for q=0; q adds 256

    const float mu1  = mu[0];
    const float nmu2 = -mu[1];
    const float dt   = DT;

    float* ys  = out;
    float* tev = out + (size_t)TT * NN * 3;
    float* yev = tev + MAXS;
    float* et  = yev + (size_t)MAXS * NN * 3;
    float* nsp = et  + (size_t)MAXS * NN;

    // zero the slot ring, then cluster-sync before anyone publishes
    for (int i = t; i < DEPTH * NSLOTS; i += NPC) slots[i] = 0u;
    const unsigned sbase = smem_u32(slots);
    // lanes 0..1 each inject the publish into one CTA of the pair
    const unsigned my_peer = mapa_u32(sbase, (unsigned)(lane & 1));
    const unsigned my_slot_off = (unsigned)(cta * WARPS + wid) * 4u;
    asm volatile("barrier.cluster.arrive.aligned;" ::: "memory");
    asm volatile("barrier.cluster.wait.aligned;"   ::: "memory");

    // Carried per-neuron state (end of step k-1):
    float v[NPT], s[NPT], i1c[NPT], i0v[NPT], v1s[NPT], s1s[NPT];
    bool  maskp[NPT];
    #pragma unroll
    for (int q = 0; q < NPT; ++q) {
        int n = nb + q * NPC;
        v[q]   = v0[n];
        s[q]   = __fsub_rn(logf(u0[n]), ALPHA_F);
        i0v[q] = i0[n];
        i1c[q] = 0.0f; v1s[q] = 0.0f; s1s[q] = 0.0f; maskp[q] = false;
    }
    int cnt = 0;

    // prefetch ring: ic/u for steps 0..PF-1 (flattened [q][p])
    float icb[NPT * PF], ub[NPT * PF];
    #pragma unroll
    for (int j = 0; j < PF; ++j)
        #pragma unroll
        for (int q = 0; q < NPT; ++q) {
            icb[q * PF + j] = __ldg(&ic[(size_t)j * NN + nb + q * NPC]);
            ub[q * PF + j]  = __ldg(&ur[(size_t)j * NN + nb + q * NPC]);
        }

    // ---------------- peeled k = 0 (no resolve: i2 = i0) ----------------
    {
        unsigned code = 0xFFFu;
        float s1[NPT]; bool mask[NPT];
        #pragma unroll
        for (int q = NPT - 1; q >= 0; --q) {     // descending: lowest q wins
            float sp = softplus_ref(v[q]);
            s1[q]   = __fadd_rn(s[q], __fmul_rn(dt, sp));
            mask[q] = (s1[q] >= 0.0f);
            unsigned bal = __ballot_sync(FULLM, mask[q]);
            if (bal) code = (unsigned)(cta * NPCN + q * NPC + wid * 32) + (unsigned)__ffs(bal);
        }
        unsigned val = (1u << 12) | code;
        if (lane < C_CTAS) st_shared_cluster(my_peer + my_slot_off, val);

        #pragma unroll
        for (int q = 0; q < NPT; ++q) {
            float lu  = __fsub_rn(logf(ub[q * PF + 0]), ALPHA_F);
            float ick = icb[q * PF + 0];
            icb[q * PF + 0] = __ldg(&ic[(size_t)PF * NN + nb + q * NPC]);
            ub[q * PF + 0]  = __ldg(&ur[(size_t)PF * NN + nb + q * NPC]);

            float t1  = __fsub_rn(__fadd_rn(i0v[q], ick), v[q]);
            float v1  = __fadd_rn(v[q], __fmul_rn(dt, __fmul_rn(mu1, t1)));
            float i1n = __fadd_rn(i0v[q], __fmul_rn(dt, __fmul_rn(nmu2, i0v[q])));
            float v2  = mask[q] ? __fsub_rn(v1, 1.0f) : v1;
            float s2  = mask[q] ? lu : s1[q];
            v1s[q] = v1; s1s[q] = s1[q]; maskp[q] = mask[q];
            v[q] = v2; i1c[q] = i1n; s[q] = s2;
        }
    }

    // ---------------- main loop k = 1 .. TT-1 ----------------
    #pragma unroll 4
    for (int k = 1; k < TT; ++k) {
        const int p = k & (PF - 1);

        // ---- publish step k FIRST (needs only carried v, s) ----
        unsigned code = 0xFFFu;
        float s1[NPT]; bool mask[NPT];
        #pragma unroll
        for (int q = NPT - 1; q >= 0; --q) {
            float sp = softplus_ref(v[q]);
            s1[q]   = __fadd_rn(s[q], __fmul_rn(dt, sp));
            mask[q] = (s1[q] >= 0.0f);
            unsigned bal = __ballot_sync(FULLM, mask[q]);
            if (bal) code = (unsigned)(cta * NPCN + q * NPC + wid * 32) + (unsigned)__ffs(bal);
        }
        unsigned val = ((unsigned)(k + 1) << 12) | code;
        if (lane < C_CTAS)
            st_shared_cluster(my_peer + (unsigned)((k & (DEPTH - 1)) * NSLOTS) * 4u
                                      + my_slot_off, val);

        // ---- off-chain work while the publish propagates ----
        float lu[NPT], ick[NPT];
        int kp = (k + PF < TT) ? (k + PF) : (TT - 1);
        #pragma unroll
        for (int q = 0; q < NPT; ++q) {
            lu[q]  = __fsub_rn(logf(ub[q * PF + p]), ALPHA_F);
            ick[q] = icb[q * PF + p];
            icb[q * PF + p] = __ldg(&ic[(size_t)kp * NN + nb + q * NPC]);
            ub[q * PF + p]  = __ldg(&ur[(size_t)kp * NN + nb + q * NPC]);
        }

        // ---- resolve step k-1: poll local smem, then w gather ----
        const unsigned want = (unsigned)k << 12;       // tag of step k-1
        const unsigned boff = sbase + (unsigned)(((k - 1) & (DEPTH - 1)) * NSLOTS) * 4u
                                    + (unsigned)(lane & (NSLOTS - 1)) * 4u;
        unsigned a;
        do { a = ld_vol_shared(boff); }
        while (__ballot_sync(FULLM, ((a ^ want) & 0xFFFFF000u) != 0u));
        unsigned m = __reduce_min_sync(FULLM, a);
        unsigned ecode = m & 0xFFFu;
        bool eventp = (ecode != 0xFFFu);
        unsigned row = eventp ? (ecode - 1u) : 0u;     // unconditional, row 0 L1-hot
        float wv[NPT];
        #pragma unroll
        for (int q = 0; q < NPT; ++q) {
            float wraw = __ldg(&w[(size_t)row * NN + nb + q * NPC]);
            wv[q] = eventp ? wraw : 0.0f;
        }

        bool dowrite = eventp && (cnt < MAXS);
        // ---- per-neuron: consume w, advance, outputs ----
        #pragma unroll
        for (int q = 0; q < NPT; ++q) {
            int n = nb + q * NPC;
            float ysv = v[q], yss = s[q], i1old = i1c[q];
            float i2  = __fadd_rn(i1old, wv[q]);       // +0 exact when no event

            float t1  = __fsub_rn(__fadd_rn(i2, ick[q]), v[q]);
            float v1  = __fadd_rn(v[q], __fmul_rn(dt, __fmul_rn(mu1, t1)));
            float i1n = __fadd_rn(i2, __fmul_rn(dt, __fmul_rn(nmu2, i2)));
            float v2  = mask[q] ? __fsub_rn(v1, 1.0f) : v1;
            float s2  = mask[q] ? lu[q] : s1[q];

            size_t ob = ((size_t)(k - 1) * NN + n) * 3;
            ys[ob + 0] = ysv;
            ys[ob + 1] = i2;
            ys[ob + 2] = yss;
            if (dowrite) {
                size_t eb = ((size_t)cnt * NN + n) * 3;
                yev[eb + 0] = v1s[q];                  // pre-transition y at event step
                yev[eb + 1] = i1old;
                yev[eb + 2] = s1s[q];
                et[(size_t)cnt * NN + n] = maskp[q] ? 1.0f : 0.0f;
            }
            v1s[q] = v1; s1s[q] = s1[q]; maskp[q] = mask[q];
            v[q] = v2; i1c[q] = i1n; s[q] = s2;
        }
        if (dowrite) {
            if (nb == 0) tev[cnt] = __fmul_rn((float)k, dt);  // ((k-1)+1)*dt
            cnt++;
        }
    }

    // ---------------- epilogue: resolve step TT-1 ----------------
    {
        const unsigned want = (unsigned)TT << 12;
        const unsigned boff = sbase + (unsigned)(((TT - 1) & (DEPTH - 1)) * NSLOTS) * 4u
                                    + (unsigned)(lane & (NSLOTS - 1)) * 4u;
        unsigned a;
        do { a = ld_vol_shared(boff); }
        while (__ballot_sync(FULLM, ((a ^ want) & 0xFFFFF000u) != 0u));
        unsigned m = __reduce_min_sync(FULLM, a);
        unsigned ecode = m & 0xFFFu;
        bool eventp = (ecode != 0xFFFu);
        bool dowrite = eventp && (cnt < MAXS);
        #pragma unroll
        for (int q = 0; q < NPT; ++q) {
            int n = nb + q * NPC;
            float wraw = eventp ? __ldg(&w[(size_t)(ecode - 1u) * NN + n]) : 0.0f;
            float i2 = __fadd_rn(i1c[q], wraw);
            size_t ob = ((size_t)(TT - 1) * NN + n) * 3;
            ys[ob + 0] = v[q];
            ys[ob + 1] = i2;
            ys[ob + 2] = s[q];
            if (dowrite) {
                size_t eb = ((size_t)cnt * NN + n) * 3;
                yev[eb + 0] = v1s[q];
                yev[eb + 1] = i1c[q];
                yev[eb + 2] = s1s[q];
                et[(size_t)cnt * NN + n] = maskp[q] ? 1.0f : 0.0f;
            }
        }
        if (dowrite) {
            if (nb == 0) tev[cnt] = __fmul_rn((float)TT, dt);
            cnt++;
        }
    }

    if (nb == 0) nsp[0] = (float)cnt;

    // no CTA may exit while the peer could still address its SMEM
    asm volatile("barrier.cluster.arrive.aligned;" ::: "memory");
    asm volatile("barrier.cluster.wait.aligned;"   ::: "memory");
}

extern "C" void kernel_launch(void* const* d_in, const int* in_sizes, int n_in,
                              void* d_out, int out_size) {
    const float* w  = (const float*)d_in[0];
    const float* mu = (const float*)d_in[1];
    const float* v0 = (const float*)d_in[2];
    const float* i0 = (const float*)d_in[3];
    const float* ic = (const float*)d_in[4];
    const float* u0 = (const float*)d_in[5];
    const float* ur = (const float*)d_in[6];
    float* out = (float*)d_out;

    init_kernel<<<512, 256>>>(out);
    sim_kernel<<<C_CTAS, NPC>>>(w, mu, v0, i0, ic, u0, ur, out);
    (void)in_sizes; (void)n_in; (void)out_size;
}

// round 13
// speedup vs baseline: 1.5274x; 1.5274x over previous
#include <cuda_runtime.h>
#include <cstdint>

#define NN 2048
#define TT 4096
#define MAXS 256
#define C_CTAS 8
#define NPC 128            /* threads per CTA */
#define NPT 2              /* neurons per thread */
#define NPCN (NPC * NPT)   /* neurons per CTA = 256 */
#define WARPS 4            /* warps per CTA */
#define NSLOTS 32          /* total publishing warps in cluster */
#define DEPTH 8            /* slot ring depth (skew bound is 2) */
#define PF 4               /* ic/ur prefetch depth (register ring) */
#define DT 2.44140625e-4f  /* (1-0)/4096, exact in fp32 */
#define ALPHA_F 0.01f
#define FULLM 0xffffffffu

__global__ void init_kernel(float* __restrict__ out) {
    int idx = blockIdx.x * blockDim.x + threadIdx.x;
    int stride = gridDim.x * blockDim.x;
    // Output layout: [ys (T*N*3)] [tev (256)] [yev (256*N*3)] [et (256*N)] [num_spikes (1)]
    float* tev = out + (size_t)TT * NN * 3;
    const int inf_n = MAXS + MAXS * NN * 3;          // tevents + yevents -> +inf
    const float finf = __int_as_float(0x7f800000);
    for (int t = idx; t < inf_n; t += stride) tev[t] = finf;
    float* et = tev + inf_n;
    const int et_n = MAXS * NN;                      // event_types -> 0
    for (int t = idx; t < et_n; t += stride) et[t] = 0.0f;
}

__device__ __forceinline__ unsigned ld_vol_shared(unsigned addr) {
    unsigned v;
    asm volatile("ld.volatile.shared.u32 %0, [%1];" : "=r"(v) : "r"(addr));
    return v;
}
__device__ __forceinline__ void st_shared_cluster(unsigned addr, unsigned v) {
    asm volatile("st.shared::cluster.u32 [%0], %1;" :: "r"(addr), "r"(v) : "memory");
}
__device__ __forceinline__ unsigned mapa_u32(unsigned addr, unsigned rank) {
    unsigned r;
    asm("mapa.shared::cluster.u32 %0, %1, %2;" : "=r"(r) : "r"(addr), "r"(rank));
    return r;
}
__device__ __forceinline__ unsigned smem_u32(const void* p) {
    unsigned a;
    asm("{ .reg .u64 t; cvta.to.shared.u64 t, %1; cvt.u32.u64 %0, t; }" : "=r"(a) : "l"(p));
    return a;
}

// Exact jax.nn.softplus(x) = max(x,0) + log1p(exp(-|x|))
__device__ __forceinline__ float softplus_ref(float v) {
    float ax = fabsf(v);
    float e  = expf(-ax);
    float l  = log1pf(e);
    return __fadd_rn(fmaxf(v, 0.0f), l);
}

__global__ void __launch_bounds__(NPC, 1) __cluster_dims__(C_CTAS, 1, 1)
sim_kernel(const float* __restrict__ w,  const float* __restrict__ mu,
           const float* __restrict__ v0, const float* __restrict__ i0,
           const float* __restrict__ ic, const float* __restrict__ u0,
           const float* __restrict__ ur, float* __restrict__ out)
{
    __shared__ __align__(16) unsigned slots[DEPTH * NSLOTS];  // [ring][32 warp slots]

    const int t    = threadIdx.x;
    const int lane = t & 31;
    const int wid  = t >> 5;                     // 0..3
    const int cta  = blockIdx.x;                 // cluster rank (grid == 1 cluster)
    const int nb   = cta * NPCN + t;             // neuron for q=0; q adds 128

    const float mu1  = mu[0];
    const float nmu2 = -mu[1];
    const float dt   = DT;

    float* ys  = out;
    float* tev = out + (size_t)TT * NN * 3;
    float* yev = tev + MAXS;
    float* et  = yev + (size_t)MAXS * NN * 3;
    float* nsp = et  + (size_t)MAXS * NN;

    // zero the slot ring, then cluster-sync before anyone publishes
    for (int i = t; i < DEPTH * NSLOTS; i += NPC) slots[i] = 0u;
    const unsigned sbase = smem_u32(slots);
    // lanes 0..7 each inject the publish into one peer CTA
    const unsigned my_peer = mapa_u32(sbase, (unsigned)(lane & 7));
    const unsigned my_slot_off = (unsigned)(cta * WARPS + wid) * 4u;
    asm volatile("barrier.cluster.arrive.aligned;" ::: "memory");
    asm volatile("barrier.cluster.wait.aligned;"   ::: "memory");

    // Carried per-neuron state (end of step k-1):
    float v[NPT], s[NPT], i1c[NPT], i0v[NPT], v1s[NPT], s1s[NPT];
    bool  maskp[NPT];
    #pragma unroll
    for (int q = 0; q < NPT; ++q) {
        int n = nb + q * NPC;
        v[q]   = v0[n];
        s[q]   = __fsub_rn(logf(u0[n]), ALPHA_F);
        i0v[q] = i0[n];
        i1c[q] = 0.0f; v1s[q] = 0.0f; s1s[q] = 0.0f; maskp[q] = false;
    }
    int cnt = 0;

    // prefetch ring: ic/u for steps 0..PF-1 (flattened [q][p])
    float icb[NPT * PF], ub[NPT * PF];
    #pragma unroll
    for (int j = 0; j < PF; ++j)
        #pragma unroll
        for (int q = 0; q < NPT; ++q) {
            icb[q * PF + j] = __ldg(&ic[(size_t)j * NN + nb + q * NPC]);
            ub[q * PF + j]  = __ldg(&ur[(size_t)j * NN + nb + q * NPC]);
        }

    // ---------------- peeled k = 0 (no resolve: i2 = i0) ----------------
    {
        unsigned code = 0xFFFu;
        float s1[NPT]; bool mask[NPT];
        #pragma unroll
        for (int q = NPT - 1; q >= 0; --q) {     // descending: lowest q wins
            float sp = softplus_ref(v[q]);
            s1[q]   = __fadd_rn(s[q], __fmul_rn(dt, sp));
            mask[q] = (s1[q] >= 0.0f);
            unsigned bal = __ballot_sync(FULLM, mask[q]);
            if (bal) code = (unsigned)(cta * NPCN + q * NPC + wid * 32) + (unsigned)__ffs(bal);
        }
        unsigned val = (1u << 12) | code;
        if (lane < C_CTAS) st_shared_cluster(my_peer + my_slot_off, val);

        #pragma unroll
        for (int q = 0; q < NPT; ++q) {
            float lu  = __fsub_rn(logf(ub[q * PF + 0]), ALPHA_F);
            float ick = icb[q * PF + 0];
            icb[q * PF + 0] = __ldg(&ic[(size_t)PF * NN + nb + q * NPC]);
            ub[q * PF + 0]  = __ldg(&ur[(size_t)PF * NN + nb + q * NPC]);

            float t1  = __fsub_rn(__fadd_rn(i0v[q], ick), v[q]);
            float v1  = __fadd_rn(v[q], __fmul_rn(dt, __fmul_rn(mu1, t1)));
            float i1n = __fadd_rn(i0v[q], __fmul_rn(dt, __fmul_rn(nmu2, i0v[q])));
            float v2  = mask[q] ? __fsub_rn(v1, 1.0f) : v1;
            float s2  = mask[q] ? lu : s1[q];
            v1s[q] = v1; s1s[q] = s1[q]; maskp[q] = mask[q];
            v[q] = v2; i1c[q] = i1n; s[q] = s2;
        }
    }

    // ---------------- main loop k = 1 .. TT-1 ----------------
    #pragma unroll 4
    for (int k = 1; k < TT; ++k) {
        const int p = k & (PF - 1);

        // ---- publish step k FIRST (needs only carried v, s) ----
        unsigned code = 0xFFFu;
        float s1[NPT]; bool mask[NPT];
        #pragma unroll
        for (int q = NPT - 1; q >= 0; --q) {
            float sp = softplus_ref(v[q]);
            s1[q]   = __fadd_rn(s[q], __fmul_rn(dt, sp));
            mask[q] = (s1[q] >= 0.0f);
            unsigned bal = __ballot_sync(FULLM, mask[q]);
            if (bal) code = (unsigned)(cta * NPCN + q * NPC + wid * 32) + (unsigned)__ffs(bal);
        }
        unsigned val = ((unsigned)(k + 1) << 12) | code;
        if (lane < C_CTAS)
            st_shared_cluster(my_peer + (unsigned)((k & (DEPTH - 1)) * NSLOTS) * 4u
                                      + my_slot_off, val);

        // ---- off-chain work while the publish propagates ----
        float lu[NPT], ick[NPT];
        int kp = (k + PF < TT) ? (k + PF) : (TT - 1);
        #pragma unroll
        for (int q = 0; q < NPT; ++q) {
            lu[q]  = __fsub_rn(logf(ub[q * PF + p]), ALPHA_F);
            ick[q] = icb[q * PF + p];
            icb[q * PF + p] = __ldg(&ic[(size_t)kp * NN + nb + q * NPC]);
            ub[q * PF + p]  = __ldg(&ur[(size_t)kp * NN + nb + q * NPC]);
        }

        // ---- resolve step k-1: poll local smem (1 LDS/spin), then w gather ----
        const unsigned want = (unsigned)k << 12;       // tag of step k-1
        const unsigned boff = sbase + (unsigned)(((k - 1) & (DEPTH - 1)) * NSLOTS) * 4u
                                    + (unsigned)lane * 4u;
        unsigned a;
        do { a = ld_vol_shared(boff); }
        while (__ballot_sync(FULLM, ((a ^ want) & 0xFFFFF000u) != 0u));
        unsigned m = __reduce_min_sync(FULLM, a);
        unsigned ecode = m & 0xFFFu;
        bool eventp = (ecode != 0xFFFu);
        unsigned row = eventp ? (ecode - 1u) : 0u;     // unconditional, row 0 L1-hot
        float wv[NPT];
        #pragma unroll
        for (int q = 0; q < NPT; ++q) {
            float wraw = __ldg(&w[(size_t)row * NN + nb + q * NPC]);
            wv[q] = eventp ? wraw : 0.0f;
        }

        bool dowrite = eventp && (cnt < MAXS);
        // ---- per-neuron: consume w, advance, outputs ----
        #pragma unroll
        for (int q = 0; q < NPT; ++q) {
            int n = nb + q * NPC;
            float ysv = v[q], yss = s[q], i1old = i1c[q];
            float i2  = __fadd_rn(i1old, wv[q]);       // +0 exact when no event

            float t1  = __fsub_rn(__fadd_rn(i2, ick[q]), v[q]);
            float v1  = __fadd_rn(v[q], __fmul_rn(dt, __fmul_rn(mu1, t1)));
            float i1n = __fadd_rn(i2, __fmul_rn(dt, __fmul_rn(nmu2, i2)));
            float v2  = mask[q] ? __fsub_rn(v1, 1.0f) : v1;
            float s2  = mask[q] ? lu[q] : s1[q];

            size_t ob = ((size_t)(k - 1) * NN + n) * 3;
            ys[ob + 0] = ysv;
            ys[ob + 1] = i2;
            ys[ob + 2] = yss;
            if (dowrite) {
                size_t eb = ((size_t)cnt * NN + n) * 3;
                yev[eb + 0] = v1s[q];                  // pre-transition y at event step
                yev[eb + 1] = i1old;
                yev[eb + 2] = s1s[q];
                et[(size_t)cnt * NN + n] = maskp[q] ? 1.0f : 0.0f;
            }
            v1s[q] = v1; s1s[q] = s1[q]; maskp[q] = mask[q];
            v[q] = v2; i1c[q] = i1n; s[q] = s2;
        }
        if (dowrite) {
            if (nb == 0) tev[cnt] = __fmul_rn((float)k, dt);  // ((k-1)+1)*dt
            cnt++;
        }
    }

    // ---------------- epilogue: resolve step TT-1 ----------------
    {
        const unsigned want = (unsigned)TT << 12;
        const unsigned boff = sbase + (unsigned)(((TT - 1) & (DEPTH - 1)) * NSLOTS) * 4u
                                    + (unsigned)lane * 4u;
        unsigned a;
        do { a = ld_vol_shared(boff); }
        while (__ballot_sync(FULLM, ((a ^ want) & 0xFFFFF000u) != 0u));
        unsigned m = __reduce_min_sync(FULLM, a);
        unsigned ecode = m & 0xFFFu;
        bool eventp = (ecode != 0xFFFu);
        bool dowrite = eventp && (cnt < MAXS);
        #pragma unroll
        for (int q = 0; q < NPT; ++q) {
            int n = nb + q * NPC;
            float wraw = eventp ? __ldg(&w[(size_t)(ecode - 1u) * NN + n]) : 0.0f;
            float i2 = __fadd_rn(i1c[q], wraw);
            size_t ob = ((size_t)(TT - 1) * NN + n) * 3;
            ys[ob + 0] = v[q];
            ys[ob + 1] = i2;
            ys[ob + 2] = s[q];
            if (dowrite) {
                size_t eb = ((size_t)cnt * NN + n) * 3;
                yev[eb + 0] = v1s[q];
                yev[eb + 1] = i1c[q];
                yev[eb + 2] = s1s[q];
                et[(size_t)cnt * NN + n] = maskp[q] ? 1.0f : 0.0f;
            }
        }
        if (dowrite) {
            if (nb == 0) tev[cnt] = __fmul_rn((float)TT, dt);
            cnt++;
        }
    }

    if (nb == 0) nsp[0] = (float)cnt;

    // no CTA may exit while peers could still address its SMEM
    asm volatile("barrier.cluster.arrive.aligned;" ::: "memory");
    asm volatile("barrier.cluster.wait.aligned;"   ::: "memory");
}

extern "C" void kernel_launch(void* const* d_in, const int* in_sizes, int n_in,
                              void* d_out, int out_size) {
    const float* w  = (const float*)d_in[0];
    const float* mu = (const float*)d_in[1];
    const float* v0 = (const float*)d_in[2];
    const float* i0 = (const float*)d_in[3];
    const float* ic = (const float*)d_in[4];
    const float* u0 = (const float*)d_in[5];
    const float* ur = (const float*)d_in[6];
    float* out = (float*)d_out;

    init_kernel<<<512, 256>>>(out);
    sim_kernel<<<C_CTAS, NPC>>>(w, mu, v0, i0, ic, u0, ur, out);
    (void)in_sizes; (void)n_in; (void)out_size;
}